// round 2
// baseline (speedup 1.0000x reference)
#include <cuda_runtime.h>

#define N_NODES 100000
#define N_EDGES 1000000
#define D_FEAT 64

// Scratch (allocation-free rule: __device__ globals)
__device__ float g_ex[N_EDGES];
__device__ float g_sum[N_NODES];

// ---------------------------------------------------------------------------
// Pass 1: per-edge dot product, e = exp(-0.01*|dot|), ex = exp(e),
//         atomicAdd into per-dst segment sum.
// 8 lanes cooperate per edge; stride-8 float4 loads so each LDG.128 across
// the 8-lane group covers one contiguous 128B line of the 256B row.
// Softmax is shift-invariant and e is bounded in (0.6, 1], so the reference's
// segment-max pass is mathematically unnecessary — skipped exactly.
// ---------------------------------------------------------------------------
__global__ __launch_bounds__(256)
void edge_kernel(const float* __restrict__ feats,
                 const int* __restrict__ src,
                 const int* __restrict__ dst) {
    int tid = blockIdx.x * blockDim.x + threadIdx.x;
    int eid = tid >> 3;      // 8 lanes per edge
    int sub = tid & 7;
    if (eid >= N_EDGES) return;

    int s = __ldg(src + eid);
    int d = __ldg(dst + eid);

    const float4* fs = reinterpret_cast<const float4*>(feats + (size_t)s * D_FEAT);
    const float4* fd = reinterpret_cast<const float4*>(feats + (size_t)d * D_FEAT);

    // Row = 16 float4s. Lane `sub` takes elements sub and sub+8.
    float4 a0 = fs[sub];
    float4 a1 = fs[sub + 8];
    float4 b0 = fd[sub];
    float4 b1 = fd[sub + 8];

    float acc = a0.x * b0.x + a0.y * b0.y + a0.z * b0.z + a0.w * b0.w
              + a1.x * b1.x + a1.y * b1.y + a1.z * b1.z + a1.w * b1.w;

    // Reduce across the 8-lane group
    acc += __shfl_down_sync(0xFFFFFFFFu, acc, 4);
    acc += __shfl_down_sync(0xFFFFFFFFu, acc, 2);
    acc += __shfl_down_sync(0xFFFFFFFFu, acc, 1);

    if (sub == 0) {
        float e  = __expf(-0.01f * fabsf(acc));   // in (0.6, 1]
        float ex = __expf(e);                     // in (1.9, 2.8)
        g_ex[eid] = ex;
        atomicAdd(&g_sum[d], ex);
    }
}

// ---------------------------------------------------------------------------
// Pass 2: out[e] = ex[e] / sum[dst[e]], 4 edges per thread (vectorized).
// N_EDGES is divisible by 4, so no tail handling needed.
// ---------------------------------------------------------------------------
__global__ __launch_bounds__(256)
void div_kernel(const int* __restrict__ dst,
                float* __restrict__ out) {
    int i = blockIdx.x * blockDim.x + threadIdx.x;   // vec4 index
    if (i * 4 >= N_EDGES) return;

    int4   d4 = reinterpret_cast<const int4*>(dst)[i];
    float4 e4 = reinterpret_cast<const float4*>(g_ex)[i];

    float4 o;
    o.x = e4.x / g_sum[d4.x];
    o.y = e4.y / g_sum[d4.y];
    o.z = e4.z / g_sum[d4.z];
    o.w = e4.w / g_sum[d4.w];

    reinterpret_cast<float4*>(out)[i] = o;
}

// ---------------------------------------------------------------------------
extern "C" void kernel_launch(void* const* d_in, const int* in_sizes, int n_in,
                              void* d_out, int out_size) {
    const float* feats = (const float*)d_in[0];
    const int*   src   = (const int*)d_in[1];
    const int*   dst   = (const int*)d_in[2];
    float* out = (float*)d_out;

    // Zero the segment sums via an async memset (graph memset node — far
    // cheaper to dispatch than a kernel launch; not an allocation).
    void* sum_ptr = nullptr;
    cudaGetSymbolAddress(&sum_ptr, g_sum);
    cudaMemsetAsync(sum_ptr, 0, N_NODES * sizeof(float));

    edge_kernel<<<(N_EDGES * 8 + 255) / 256, 256>>>(feats, src, dst);

    const int nvec = N_EDGES / 4;
    div_kernel<<<(nvec + 255) / 256, 256>>>(dst, out);
}

// round 3
// speedup vs baseline: 1.0959x; 1.0959x over previous
#include <cuda_runtime.h>
#include <cuda_fp16.h>

#define N_NODES 100000
#define N_EDGES 1000000
#define D_FEAT 64

// Scratch (allocation-free rule: __device__ globals)
__device__ __half g_hfeats[N_NODES * D_FEAT];   // 12.8 MB fp16 feature table
__device__ float  g_ex[N_EDGES];
__device__ float  g_sum[N_NODES];

// ---------------------------------------------------------------------------
// Pass 0b: convert feats fp32 -> fp16 table. 4 elements per thread.
// 6.4M elements / 4 = 1.6M threads. Pure streaming: 25.6MB R + 12.8MB W.
// ---------------------------------------------------------------------------
__global__ __launch_bounds__(256)
void convert_kernel(const float* __restrict__ feats) {
    int i = blockIdx.x * blockDim.x + threadIdx.x;           // float4 index
    if (i >= (N_NODES * D_FEAT) / 4) return;
    float4 f = reinterpret_cast<const float4*>(feats)[i];
    half2 h0 = __floats2half2_rn(f.x, f.y);
    half2 h1 = __floats2half2_rn(f.z, f.w);
    uint2 packed = make_uint2(*reinterpret_cast<unsigned*>(&h0),
                              *reinterpret_cast<unsigned*>(&h1));
    reinterpret_cast<uint2*>(g_hfeats)[i] = packed;
}

// ---------------------------------------------------------------------------
// Pass 1: per-edge dot (fp16 loads, fp32 accumulate), ex = exp(exp(-0.01|dot|)),
//         atomicAdd into per-dst segment sum.
// 4 lanes per edge. Row = 128B = 8 float4s of half data; lane `sub` takes
// float4s sub and sub+4 -> the 4-lane group covers the row with contiguous
// LDG.128s. Segment-max pass skipped: softmax is shift-invariant and
// e in (0.6, 1] needs no stabilization.
// ---------------------------------------------------------------------------
__device__ __forceinline__ float dot8h(float4 a, float4 b) {
    const half2* pa = reinterpret_cast<const half2*>(&a);
    const half2* pb = reinterpret_cast<const half2*>(&b);
    float acc = 0.0f;
#pragma unroll
    for (int i = 0; i < 4; i++) {
        float2 fa = __half22float2(pa[i]);
        float2 fb = __half22float2(pb[i]);
        acc = fmaf(fa.x, fb.x, acc);
        acc = fmaf(fa.y, fb.y, acc);
    }
    return acc;
}

__global__ __launch_bounds__(256)
void edge_kernel(const int* __restrict__ src,
                 const int* __restrict__ dst) {
    int tid = blockIdx.x * blockDim.x + threadIdx.x;
    int eid = tid >> 2;      // 4 lanes per edge
    int sub = tid & 3;
    if (eid >= N_EDGES) return;

    int s = __ldg(src + eid);
    int d = __ldg(dst + eid);

    const float4* fs = reinterpret_cast<const float4*>(g_hfeats + (size_t)s * D_FEAT);
    const float4* fd = reinterpret_cast<const float4*>(g_hfeats + (size_t)d * D_FEAT);

    float4 a0 = fs[sub];
    float4 a1 = fs[sub + 4];
    float4 b0 = fd[sub];
    float4 b1 = fd[sub + 4];

    float acc = dot8h(a0, b0) + dot8h(a1, b1);

    // Reduce across the 4-lane group
    acc += __shfl_down_sync(0xFFFFFFFFu, acc, 2);
    acc += __shfl_down_sync(0xFFFFFFFFu, acc, 1);

    if (sub == 0) {
        float e  = __expf(-0.01f * fabsf(acc));   // in (0.6, 1]
        float ex = __expf(e);                     // in (1.9, 2.8)
        g_ex[eid] = ex;
        atomicAdd(&g_sum[d], ex);
    }
}

// ---------------------------------------------------------------------------
// Pass 2: out[e] = ex[e] / sum[dst[e]], 1 edge per thread (max latency hiding
// for the random L2-resident g_sum gather).
// ---------------------------------------------------------------------------
__global__ __launch_bounds__(256)
void div_kernel(const int* __restrict__ dst,
                float* __restrict__ out) {
    int i = blockIdx.x * blockDim.x + threadIdx.x;
    if (i < N_EDGES) {
        out[i] = g_ex[i] / g_sum[__ldg(dst + i)];
    }
}

// ---------------------------------------------------------------------------
extern "C" void kernel_launch(void* const* d_in, const int* in_sizes, int n_in,
                              void* d_out, int out_size) {
    const float* feats = (const float*)d_in[0];
    const int*   src   = (const int*)d_in[1];
    const int*   dst   = (const int*)d_in[2];
    float* out = (float*)d_out;

    void* sum_ptr = nullptr;
    cudaGetSymbolAddress(&sum_ptr, g_sum);
    cudaMemsetAsync(sum_ptr, 0, N_NODES * sizeof(float));

    convert_kernel<<<((N_NODES * D_FEAT / 4) + 255) / 256, 256>>>(feats);
    edge_kernel<<<(N_EDGES * 4 + 255) / 256, 256>>>(src, dst);
    div_kernel<<<(N_EDGES + 255) / 256, 256>>>(dst, out);
}

// round 4
// speedup vs baseline: 1.0995x; 1.0033x over previous
#include <cuda_runtime.h>
#include <cuda_fp16.h>

#define N_NODES 100000
#define N_EDGES 1000000
#define D_FEAT 64

// Scratch (allocation-free rule: __device__ globals)
__device__ __half g_hfeats[N_NODES * D_FEAT];   // 12.8 MB fp16 feature table
__device__ __half g_exh[N_EDGES];               // 2 MB per-edge ex (fp16)
__device__ float  g_sum[N_NODES];

// ---------------------------------------------------------------------------
// Pass 0b: convert feats fp32 -> fp16. 8 elements per thread:
// two LDG.128 (streaming hint, no reuse) -> one STG.128 of 8 packed halves.
// 6.4M elems / 8 = 800k threads.
// ---------------------------------------------------------------------------
__global__ __launch_bounds__(256)
void convert_kernel(const float* __restrict__ feats) {
    int i = blockIdx.x * blockDim.x + threadIdx.x;           // 8-elem index
    if (i >= (N_NODES * D_FEAT) / 8) return;

    const float4* in = reinterpret_cast<const float4*>(feats) + i * 2;
    float4 f0 = __ldcs(in);
    float4 f1 = __ldcs(in + 1);

    half2 h0 = __floats2half2_rn(f0.x, f0.y);
    half2 h1 = __floats2half2_rn(f0.z, f0.w);
    half2 h2 = __floats2half2_rn(f1.x, f1.y);
    half2 h3 = __floats2half2_rn(f1.z, f1.w);

    uint4 packed;
    packed.x = *reinterpret_cast<unsigned*>(&h0);
    packed.y = *reinterpret_cast<unsigned*>(&h1);
    packed.z = *reinterpret_cast<unsigned*>(&h2);
    packed.w = *reinterpret_cast<unsigned*>(&h3);
    reinterpret_cast<uint4*>(g_hfeats)[i] = packed;
}

// ---------------------------------------------------------------------------
// Pass 1: per-edge dot (fp16 loads, fp32 FMA), ex = exp(exp(-0.01|dot|)),
//         atomicAdd into per-dst segment sum.
// 4 lanes per edge; row = 128B = 8 float4s of half data; lane `sub` takes
// float4s sub and sub+4 so the quad covers the row with contiguous LDG.128s.
// Segment-max pass skipped exactly (softmax shift-invariance; e in (0.6,1]).
// ex rounded to fp16 and the SAME rounded value fed to the atomic sum, so
// numerator/denominator stay consistent and rounding cancels in the ratio.
// ---------------------------------------------------------------------------
__device__ __forceinline__ float dot8h(float4 a, float4 b) {
    const half2* pa = reinterpret_cast<const half2*>(&a);
    const half2* pb = reinterpret_cast<const half2*>(&b);
    float acc = 0.0f;
#pragma unroll
    for (int i = 0; i < 4; i++) {
        float2 fa = __half22float2(pa[i]);
        float2 fb = __half22float2(pb[i]);
        acc = fmaf(fa.x, fb.x, acc);
        acc = fmaf(fa.y, fb.y, acc);
    }
    return acc;
}

__global__ __launch_bounds__(256)
void edge_kernel(const int* __restrict__ src,
                 const int* __restrict__ dst) {
    int tid = blockIdx.x * blockDim.x + threadIdx.x;
    int eid = tid >> 2;      // 4 lanes per edge
    int sub = tid & 3;
    if (eid >= N_EDGES) return;

    int s = __ldg(src + eid);
    int d = __ldg(dst + eid);

    const float4* fs = reinterpret_cast<const float4*>(g_hfeats + (size_t)s * D_FEAT);
    const float4* fd = reinterpret_cast<const float4*>(g_hfeats + (size_t)d * D_FEAT);

    float4 a0 = fs[sub];
    float4 a1 = fs[sub + 4];
    float4 b0 = fd[sub];
    float4 b1 = fd[sub + 4];

    float acc = dot8h(a0, b0) + dot8h(a1, b1);

    acc += __shfl_down_sync(0xFFFFFFFFu, acc, 2);
    acc += __shfl_down_sync(0xFFFFFFFFu, acc, 1);

    if (sub == 0) {
        float e   = __expf(-0.01f * fabsf(acc));  // in (0.6, 1]
        float ex  = __expf(e);                    // in (1.9, 2.8)
        __half h  = __float2half_rn(ex);
        float exr = __half2float(h);              // the value both sides will see
        g_exh[eid] = h;
        atomicAdd(&g_sum[d], exr);
    }
}

// ---------------------------------------------------------------------------
// Pass 2: out[e] = ex[e] / sum[dst[e]], 1 edge/thread (max warps in flight to
// hide the random L2-resident g_sum gather latency).
// ---------------------------------------------------------------------------
__global__ __launch_bounds__(256)
void div_kernel(const int* __restrict__ dst,
                float* __restrict__ out) {
    int i = blockIdx.x * blockDim.x + threadIdx.x;
    if (i < N_EDGES) {
        out[i] = __half2float(g_exh[i]) / g_sum[__ldg(dst + i)];
    }
}

// ---------------------------------------------------------------------------
extern "C" void kernel_launch(void* const* d_in, const int* in_sizes, int n_in,
                              void* d_out, int out_size) {
    const float* feats = (const float*)d_in[0];
    const int*   src   = (const int*)d_in[1];
    const int*   dst   = (const int*)d_in[2];
    float* out = (float*)d_out;

    void* sum_ptr = nullptr;
    cudaGetSymbolAddress(&sum_ptr, g_sum);
    cudaMemsetAsync(sum_ptr, 0, N_NODES * sizeof(float));

    convert_kernel<<<((N_NODES * D_FEAT / 8) + 255) / 256, 256>>>(feats);
    edge_kernel<<<(N_EDGES * 4 + 255) / 256, 256>>>(src, dst);
    div_kernel<<<(N_EDGES + 255) / 256, 256>>>(dst, out);
}